// round 7
// baseline (speedup 1.0000x reference)
#include <cuda_runtime.h>
#include <cuda_fp16.h>
#include <cstdint>

// ---------------------------------------------------------------------------
// Problem constants
// ---------------------------------------------------------------------------
#define M_TOK   64
#define KDIM    8192
#define NOUT    14336
#define KW      (KDIM / 2)          // 4096 int32 per output row
#define NTILE   128
#define GRID_N  (NOUT / NTILE)      // 112 CTAs = one wave

// SMEM rings: weights 4 x 32KB, x 4 x 16KB  => 192 KB dynamic
#define WSTAGE  32768
#define XOFF    131072
#define XSTAGE  16384
#define SMEM_TOTAL 196608

// x (fp16, k-permuted + bank-swizzled) staged per 64-k chunk: 128 chunks x 8KB
__device__ __align__(16) unsigned char g_ximg[(size_t)M_TOK * KDIM * 2];  // 1 MB

// ---------------------------------------------------------------------------
// Helpers
// ---------------------------------------------------------------------------
__device__ __forceinline__ void cp16(uint32_t saddr, const void* g) {
    asm volatile("cp.async.cg.shared.global [%0], [%1], 16;" :: "r"(saddr), "l"(g));
}
__device__ __forceinline__ void cp_commit() {
    asm volatile("cp.async.commit_group;" ::: "memory");
}
__device__ __forceinline__ uint2 lds64(uint32_t addr) {
    uint2 r;
    asm volatile("ld.shared.v2.u32 {%0,%1}, [%2];" : "=r"(r.x), "=r"(r.y) : "r"(addr));
    return r;
}
__device__ __forceinline__ uint4 lds128(uint32_t addr) {
    uint4 r;
    asm volatile("ld.shared.v4.u32 {%0,%1,%2,%3}, [%4];"
                 : "=r"(r.x), "=r"(r.y), "=r"(r.z), "=r"(r.w) : "r"(addr));
    return r;
}
__device__ __forceinline__ void mma16816(float* d, uint32_t a0, uint32_t a1,
                                         uint32_t a2, uint32_t a3,
                                         uint32_t b0, uint32_t b1) {
    asm volatile(
        "mma.sync.aligned.m16n8k16.row.col.f32.f16.f16.f32 "
        "{%0,%1,%2,%3}, {%4,%5,%6,%7}, {%8,%9}, {%0,%1,%2,%3};"
        : "+f"(d[0]), "+f"(d[1]), "+f"(d[2]), "+f"(d[3])
        : "r"(a0), "r"(a1), "r"(a2), "r"(a3), "r"(b0), "r"(b1));
}

// int4-pair dequant: one int32 (value 0..255; lo nibble = even k) -> f16x2 {qlo,qhi}.
// lo half = 0x6408 ^ nibLo = 1032 + qlo (exact); HSUB2 by 1032 -> exact signed int4.
__device__ __forceinline__ uint32_t dq2(uint32_t v) {
    uint32_t t = (v & 0xFu) ^ 0x64086408u;
    uint32_t p = t ^ ((v << 12) & 0x000F0000u);
    __half2 hp = *reinterpret_cast<__half2*>(&p);
    __half2 r = __hsub2(hp, __half2half2(__ushort_as_half((unsigned short)0x6408)));
    return *reinterpret_cast<uint32_t*>(&r);
}

// ---------------------------------------------------------------------------
// Pre-kernel: x [64,8192] f32 -> f16 with the k-permutation + LDS swizzle baked in.
// Chunk cc covers physical k [cc*64, cc*64+64). Granule q (q = 4c+s, c=q>>2, s=q&3)
// stores 4 halves = physical k {8c+2s, 8c+2s+1, 32+8c+2s, 33+8c+2s} at byte offset
// tok*128 + ((q ^ (tok&7)) * 8) inside the 8KB chunk tile.
// ---------------------------------------------------------------------------
__global__ void convert_x(const float* __restrict__ x) {
    int tg  = blockIdx.x * 256 + threadIdx.x;    // 131072 threads
    int cc  = tg >> 10;
    int rem = tg & 1023;
    int tok = rem >> 4;
    int q   = rem & 15;
    int c = q >> 2, s = q & 3;
    int k0 = cc * 64 + 8 * c + 2 * s;
    float2 v0 = *reinterpret_cast<const float2*>(x + (size_t)tok * KDIM + k0);
    float2 v1 = *reinterpret_cast<const float2*>(x + (size_t)tok * KDIM + k0 + 32);
    __half2 h0 = __floats2half2_rn(v0.x, v0.y);
    __half2 h1 = __floats2half2_rn(v1.x, v1.y);
    uint2 st;
    st.x = *reinterpret_cast<uint32_t*>(&h0);
    st.y = *reinterpret_cast<uint32_t*>(&h1);
    *reinterpret_cast<uint2*>(g_ximg + (size_t)cc * 8192 + tok * 128 +
                              ((q ^ (tok & 7)) << 3)) = st;
}

// ---------------------------------------------------------------------------
// Main kernel: CTA = 128 out-rows x 64 tokens, 256 threads / 8 warps in a
// 4(row) x 2(token) grid; warp tile = 32 rows x 32 tokens. K loop: 64 iters
// x 128 k. BOTH weights and x flow through 4-stage cp.async SMEM rings
// (prefetch distance > 3 iters ~ 2300 cyc >> 577-cyc DRAM latency), so
// latency hiding needs no register double-buffering and no extra warps.
//
// Weight SMEM layout (per stage): row r (0..127) occupies 256B at r*256;
// half h at +h*128; 16B granule c (0..7, int32s 4c..4c+3 of the half) at
// swizzled position (c ^ (4*(r&1))) * 16  -> conflict-free LDS.128.
// ---------------------------------------------------------------------------
__global__ __launch_bounds__(256, 1)
void qmain(const int* __restrict__ wp, const float* __restrict__ ws,
           const float* __restrict__ bias, float* __restrict__ out) {
    extern __shared__ __align__(16) unsigned char smem[];

    const int tid  = threadIdx.x;
    const int lane = tid & 31, warp = tid >> 5;
    const int wr = warp >> 1, wt = warp & 1;          // wr 0..3, wt 0..1
    const int rl = lane >> 2, cl = lane & 3;
    const int r0 = blockIdx.x * NTILE;

    const uint32_t sb = (uint32_t)__cvta_generic_to_shared(smem);

    // ---- weight LDS source addresses (within a stage) ----
    // row = wr*32 + mt*16 + rh*8 + rl ; r&1 == rl&1
    uint32_t wbase[2][2];
#pragma unroll
    for (int mt = 0; mt < 2; mt++)
#pragma unroll
        for (int rh = 0; rh < 2; rh++)
            wbase[mt][rh] = sb + (uint32_t)(wr * 32 + mt * 16 + rh * 8 + rl) * 256;
    const uint32_t gsw0 = (uint32_t)((cl ^ (4 * (rl & 1))) << 4);  // granule c=cl
    const uint32_t gsw1 = gsw0 ^ 64u;                              // granule c=cl+4

    // ---- weight cp.async: thread covers one contiguous 128B half-row ----
    const int wrow = tid >> 1;            // 0..127
    const int whalf = tid & 1;
    const int* wsrc = wp + (size_t)(r0 + wrow) * KW + whalf * 32;
    const uint32_t wdst = sb + (uint32_t)wrow * 256 + (uint32_t)whalf * 128;
    const uint32_t wsw = (uint32_t)((wrow & 1) * 4);

    // ---- x fragment addresses: token = wt*32 + nt*8 + rl; granule (4cl+s)^rl ----
    uint32_t baddr[4];
#pragma unroll
    for (int nt = 0; nt < 4; nt++)
        baddr[nt] = sb + XOFF + (uint32_t)(wt * 32 + nt * 8 + rl) * 128;
    uint32_t gq[4];
#pragma unroll
    for (int s = 0; s < 4; s++)
        gq[s] = (uint32_t)(((4 * cl + s) ^ rl) << 3);

#define ISSUE_STAGE(it_) do {                                                   \
        const uint32_t st_ = (uint32_t)((it_) & 3);                             \
        const int* wg_ = wsrc + (it_) * 64;                                     \
        const uint32_t wd_ = wdst + st_ * WSTAGE;                               \
        _Pragma("unroll")                                                       \
        for (int j_ = 0; j_ < 8; j_++)                                          \
            cp16(wd_ + (((uint32_t)j_ ^ wsw) << 4), wg_ + 4 * j_);              \
        const unsigned char* xg_ = g_ximg + (size_t)(it_) * XSTAGE + tid * 64;  \
        const uint32_t xd_ = sb + XOFF + st_ * XSTAGE + (uint32_t)tid * 64;     \
        _Pragma("unroll")                                                       \
        for (int j_ = 0; j_ < 4; j_++)                                          \
            cp16(xd_ + j_ * 16, xg_ + j_ * 16);                                 \
    } while (0)

#define LOADW(W, soffW_, h_) do {                                               \
        _Pragma("unroll")                                                       \
        for (int mt_ = 0; mt_ < 2; mt_++)                                       \
            _Pragma("unroll")                                                   \
            for (int rh_ = 0; rh_ < 2; rh_++) {                                 \
                uint32_t a_ = wbase[mt_][rh_] + (soffW_) + (h_) * 128;          \
                W[mt_][rh_][0] = lds128(a_ + gsw0);                             \
                W[mt_][rh_][1] = lds128(a_ + gsw1);                             \
            }                                                                   \
    } while (0)

#define COMP4(u4, s_) ((s_) == 0 ? (u4).x : (s_) == 1 ? (u4).y : (s_) == 2 ? (u4).z : (u4).w)

#define COMPUTE(W, sx_) do {                                                    \
        _Pragma("unroll")                                                       \
        for (int s_ = 0; s_ < 4; s_++) {                                        \
            uint32_t a00 = dq2(COMP4(W[0][0][0], s_));                          \
            uint32_t a01 = dq2(COMP4(W[0][1][0], s_));                          \
            uint32_t a02 = dq2(COMP4(W[0][0][1], s_));                          \
            uint32_t a03 = dq2(COMP4(W[0][1][1], s_));                          \
            uint32_t a10 = dq2(COMP4(W[1][0][0], s_));                          \
            uint32_t a11 = dq2(COMP4(W[1][1][0], s_));                          \
            uint32_t a12 = dq2(COMP4(W[1][0][1], s_));                          \
            uint32_t a13 = dq2(COMP4(W[1][1][1], s_));                          \
            _Pragma("unroll")                                                   \
            for (int nt_ = 0; nt_ < 4; nt_++) {                                 \
                uint2 b_ = lds64(baddr[nt_] + (sx_) + gq[s_]);                  \
                mma16816(d[0][nt_], a00, a01, a02, a03, b_.x, b_.y);            \
                mma16816(d[1][nt_], a10, a11, a12, a13, b_.x, b_.y);            \
            }                                                                   \
        } } while (0)

    uint4 W[2][2][2];
    float d[2][4][4] = {};

    // Prologue: stages 0..3 in flight (4 commit groups)
    ISSUE_STAGE(0); cp_commit();
    ISSUE_STAGE(1); cp_commit();
    ISSUE_STAGE(2); cp_commit();
    ISSUE_STAGE(3); cp_commit();

    for (int it = 0; it < 64; it++) {
        asm volatile("cp.async.wait_group 3;" ::: "memory");
        __syncthreads();
        const uint32_t soffW = (uint32_t)(it & 3) * WSTAGE;
        const uint32_t soffX = (uint32_t)(it & 3) * XSTAGE;

        LOADW(W, soffW, 0);
        COMPUTE(W, soffX);
        LOADW(W, soffW, 1);
        COMPUTE(W, soffX + 8192u);

        __syncthreads();
        if (it + 4 < 64) ISSUE_STAGE(it + 4);
        cp_commit();   // always commit: uniform group numbering for wait_group 3
    }

    // Epilogue: scale + bias, STG.32 (columns of out, sector-dense across lanes)
    float sc[2][2], bi[2][2];
#pragma unroll
    for (int mt = 0; mt < 2; mt++)
#pragma unroll
        for (int rh = 0; rh < 2; rh++) {
            int R = r0 + wr * 32 + mt * 16 + rh * 8 + rl;
            sc[mt][rh] = ws[R];
            bi[mt][rh] = bias[R];
        }
#pragma unroll
    for (int mt = 0; mt < 2; mt++) {
        const int Rb = r0 + wr * 32 + mt * 16 + rl;
#pragma unroll
        for (int nt = 0; nt < 4; nt++) {
            const int T = wt * 32 + nt * 8 + 2 * cl;
            out[(size_t)T * NOUT + Rb]           = d[mt][nt][0] * sc[mt][0] + bi[mt][0];
            out[(size_t)(T + 1) * NOUT + Rb]     = d[mt][nt][1] * sc[mt][0] + bi[mt][0];
            out[(size_t)T * NOUT + Rb + 8]       = d[mt][nt][2] * sc[mt][1] + bi[mt][1];
            out[(size_t)(T + 1) * NOUT + Rb + 8] = d[mt][nt][3] * sc[mt][1] + bi[mt][1];
        }
    }
}

// ---------------------------------------------------------------------------
extern "C" void kernel_launch(void* const* d_in, const int* in_sizes, int n_in,
                              void* d_out, int out_size) {
    (void)in_sizes; (void)n_in; (void)out_size;
    const float* x    = (const float*)d_in[0];
    const int*   wpk  = (const int*)d_in[1];
    const float* wsc  = (const float*)d_in[2];
    const float* bias = (const float*)d_in[3];
    float* out = (float*)d_out;

    cudaFuncSetAttribute(qmain, cudaFuncAttributeMaxDynamicSharedMemorySize, SMEM_TOTAL);
    convert_x<<<512, 256>>>(x);                              // 131072 threads
    qmain<<<GRID_N, 256, SMEM_TOTAL>>>(wpk, wsc, bias, out); // 112 CTAs, one wave
}

// round 8
// speedup vs baseline: 1.6013x; 1.6013x over previous
#include <cuda_runtime.h>
#include <cuda_fp16.h>
#include <cstdint>

// ---------------------------------------------------------------------------
// Problem constants
// ---------------------------------------------------------------------------
#define M_TOK   64
#define KDIM    8192
#define NOUT    14336
#define KW      (KDIM / 2)          // 4096 int32 per output row
#define NTILE   128
#define GRID_N  (NOUT / NTILE)      // 112 CTAs = one wave

// x (fp16, k-permuted + bank-swizzled) staged per 64-k chunk: 128 chunks x 8KB
__device__ __align__(16) unsigned char g_ximg[(size_t)M_TOK * KDIM * 2];  // 1 MB

// ---------------------------------------------------------------------------
// Helpers
// ---------------------------------------------------------------------------
__device__ __forceinline__ void cp16(uint32_t saddr, const void* g) {
    asm volatile("cp.async.cg.shared.global [%0], [%1], 16;" :: "r"(saddr), "l"(g));
}
__device__ __forceinline__ void cp_commit() {
    asm volatile("cp.async.commit_group;" ::: "memory");
}
__device__ __forceinline__ uint2 lds64(uint32_t addr) {
    uint2 r;
    asm volatile("ld.shared.v2.u32 {%0,%1}, [%2];" : "=r"(r.x), "=r"(r.y) : "r"(addr));
    return r;
}
__device__ __forceinline__ void mma16816(float* d, uint32_t a0, uint32_t a1,
                                         uint32_t a2, uint32_t a3,
                                         uint32_t b0, uint32_t b1) {
    asm volatile(
        "mma.sync.aligned.m16n8k16.row.col.f32.f16.f16.f32 "
        "{%0,%1,%2,%3}, {%4,%5,%6,%7}, {%8,%9}, {%0,%1,%2,%3};"
        : "+f"(d[0]), "+f"(d[1]), "+f"(d[2]), "+f"(d[3])
        : "r"(a0), "r"(a1), "r"(a2), "r"(a3), "r"(b0), "r"(b1));
}

// int4-pair dequant: one int32 (value 0..255; lo nibble = even k) -> f16x2 {qlo,qhi}.
// lo half = 0x6408 ^ nibLo = 1032 + qlo (exact); HSUB2 by 1032 -> exact signed int4.
__device__ __forceinline__ uint32_t dq2(uint32_t v) {
    uint32_t t = (v & 0xFu) ^ 0x64086408u;
    uint32_t p = t ^ ((v << 12) & 0x000F0000u);
    __half2 hp = *reinterpret_cast<__half2*>(&p);
    __half2 r = __hsub2(hp, __half2half2(__ushort_as_half((unsigned short)0x6408)));
    return *reinterpret_cast<uint32_t*>(&r);
}

// ---------------------------------------------------------------------------
// Pre-kernel: x [64,8192] f32 -> f16 with the k-permutation + LDS swizzle baked in.
// Chunk cc covers physical k [cc*64, cc*64+64). Granule q (q = 4c+s, c=q>>2, s=q&3)
// stores 4 halves = physical k {8c+2s, 8c+2s+1, 32+8c+2s, 33+8c+2s} at byte offset
// tok*128 + ((q ^ (tok&7)) * 8) inside the 8KB chunk tile.
// ---------------------------------------------------------------------------
__global__ void convert_x(const float* __restrict__ x) {
    int tg  = blockIdx.x * 256 + threadIdx.x;    // 131072 threads
    int cc  = tg >> 10;
    int rem = tg & 1023;
    int tok = rem >> 4;
    int q   = rem & 15;
    int c = q >> 2, s = q & 3;
    int k0 = cc * 64 + 8 * c + 2 * s;
    float2 v0 = *reinterpret_cast<const float2*>(x + (size_t)tok * KDIM + k0);
    float2 v1 = *reinterpret_cast<const float2*>(x + (size_t)tok * KDIM + k0 + 32);
    __half2 h0 = __floats2half2_rn(v0.x, v0.y);
    __half2 h1 = __floats2half2_rn(v1.x, v1.y);
    uint2 st;
    st.x = *reinterpret_cast<uint32_t*>(&h0);
    st.y = *reinterpret_cast<uint32_t*>(&h1);
    *reinterpret_cast<uint2*>(g_ximg + (size_t)cc * 8192 + tok * 128 +
                              ((q ^ (tok & 7)) << 3)) = st;
}

// ---------------------------------------------------------------------------
// Main kernel: CTA = 128 out-rows x 64 tokens, 256 threads / 8 warps.
// Warp grid 8(row) x 1(token): warp tile = 16 rows x 64 tokens -> each weight
// is dequanted exactly ONCE per CTA (R4 did it twice). Weights: gmem ->
// registers (4 buffers, prefetch distance = 3 half-chunks ~ >700 cyc) ->
// dq2 -> A frags. x: 2-stage cp.async SMEM ring (hot in L2).
// Half-chunk h (0..127) covers physical k [h*64, h*64+64) = int32s [h*32,+32).
// ---------------------------------------------------------------------------
__global__ __launch_bounds__(256, 1)
void qmain(const int* __restrict__ wp, const float* __restrict__ ws,
           const float* __restrict__ bias, float* __restrict__ out) {
    __shared__ __align__(16) unsigned char sB[2][16384];

    const int tid  = threadIdx.x;
    const int lane = tid & 31, wr = tid >> 5;         // wr 0..7 = row-warp
    const int rl = lane >> 2, cl = lane & 3;
    const int r0 = blockIdx.x * NTILE;

    const uint32_t sb = (uint32_t)__cvta_generic_to_shared(&sB[0][0]);

    // weight row pointers [rh]; thread owns int32s starting at 4*cl within a row
    const int* wptr[2];
#pragma unroll
    for (int rh = 0; rh < 2; rh++)
        wptr[rh] = wp + (size_t)(r0 + wr * 16 + rh * 8 + rl) * KW + 4 * cl;

    // B-fragment smem addresses: token = nt*8 + rl (all 64 tokens per warp)
    uint32_t baddr[8];
#pragma unroll
    for (int nt = 0; nt < 8; nt++)
        baddr[nt] = sb + (uint32_t)(nt * 8 + rl) * 128;
    uint32_t gq[4];
#pragma unroll
    for (int s = 0; s < 4; s++)
        gq[s] = (uint32_t)(((4 * cl + s) ^ rl) << 3);

    // LOADW: half-chunk h -> buffer W[rh][lo/hi]; guarded for tail
#define LOADW(W, h_) do {                                                       \
        if ((h_) < 128) {                                                       \
            _Pragma("unroll")                                                   \
            for (int rh_ = 0; rh_ < 2; rh_++) {                                 \
                const int* p_ = wptr[rh_] + (h_) * 32;                          \
                W[rh_][0] = *reinterpret_cast<const uint4*>(p_);                \
                W[rh_][1] = *reinterpret_cast<const uint4*>(p_ + 16);           \
            }                                                                   \
        } } while (0)

#define COMP4(u4, s_) ((s_) == 0 ? (u4).x : (s_) == 1 ? (u4).y : (s_) == 2 ? (u4).z : (u4).w)

#define COMPUTE(W, sx_) do {                                                    \
        _Pragma("unroll")                                                       \
        for (int s_ = 0; s_ < 4; s_++) {                                        \
            uint32_t a0 = dq2(COMP4(W[0][0], s_));                              \
            uint32_t a1 = dq2(COMP4(W[1][0], s_));                              \
            uint32_t a2 = dq2(COMP4(W[0][1], s_));                              \
            uint32_t a3 = dq2(COMP4(W[1][1], s_));                              \
            _Pragma("unroll")                                                   \
            for (int nt_ = 0; nt_ < 8; nt_++) {                                 \
                uint2 b_ = lds64(baddr[nt_] + (sx_) + gq[s_]);                  \
                mma16816(d[nt_], a0, a1, a2, a3, b_.x, b_.y);                   \
            }                                                                   \
        } } while (0)

#define ISSUE_X(it_, slot_) do {                                               \
        const unsigned char* xg_ = g_ximg + (size_t)(it_) * 16384 + tid * 64;  \
        const uint32_t xd_ = sb + (uint32_t)(slot_) * 16384u + (uint32_t)tid * 64; \
        cp16(xd_,      xg_);      cp16(xd_ + 16, xg_ + 16);                    \
        cp16(xd_ + 32, xg_ + 32); cp16(xd_ + 48, xg_ + 48);                    \
    } while (0)

    uint4 W0[2][2], W1[2][2], W2[2][2], W3[2][2];
    float d[8][4] = {};

    // Prologue: weight half-chunks 0..2 in registers; x stages 0 and 1 in flight
    LOADW(W0, 0);
    LOADW(W1, 1);
    LOADW(W2, 2);
    ISSUE_X(0, 0); cp_commit();
    ISSUE_X(1, 1); cp_commit();

    for (int p = 0; p < 32; p++) {
        // ---- iteration it = 2p (x stage 0; halves 4p, 4p+1) ----
        asm volatile("cp.async.wait_group 1;" ::: "memory");
        __syncthreads();
        LOADW(W3, 4 * p + 3);
        COMPUTE(W0, 0u);
        LOADW(W0, 4 * p + 4);
        COMPUTE(W1, 8192u);
        __syncthreads();
        if (2 * p + 2 < 64) ISSUE_X(2 * p + 2, 0);
        cp_commit();

        // ---- iteration it = 2p+1 (x stage 1; halves 4p+2, 4p+3) ----
        asm volatile("cp.async.wait_group 1;" ::: "memory");
        __syncthreads();
        LOADW(W1, 4 * p + 5);
        COMPUTE(W2, 16384u);
        LOADW(W2, 4 * p + 6);
        COMPUTE(W3, 16384u + 8192u);
        __syncthreads();
        if (2 * p + 3 < 64) ISSUE_X(2 * p + 3, 1);
        cp_commit();
    }

    // Epilogue: scale + bias. C frag: d[nt][0,1] = row rl, tokens 2cl,2cl+1;
    // d[nt][2,3] = row rl+8. STG lanes rl consecutive -> full 32B sectors.
    const int R0g = r0 + wr * 16 + rl;
    const float sc0 = ws[R0g],     bi0 = bias[R0g];
    const float sc1 = ws[R0g + 8], bi1 = bias[R0g + 8];
#pragma unroll
    for (int nt = 0; nt < 8; nt++) {
        const int T = nt * 8 + 2 * cl;
        out[(size_t)T * NOUT + R0g]           = d[nt][0] * sc0 + bi0;
        out[(size_t)(T + 1) * NOUT + R0g]     = d[nt][1] * sc0 + bi0;
        out[(size_t)T * NOUT + R0g + 8]       = d[nt][2] * sc1 + bi1;
        out[(size_t)(T + 1) * NOUT + R0g + 8] = d[nt][3] * sc1 + bi1;
    }
}

// ---------------------------------------------------------------------------
extern "C" void kernel_launch(void* const* d_in, const int* in_sizes, int n_in,
                              void* d_out, int out_size) {
    (void)in_sizes; (void)n_in; (void)out_size;
    const float* x    = (const float*)d_in[0];
    const int*   wpk  = (const int*)d_in[1];
    const float* wsc  = (const float*)d_in[2];
    const float* bias = (const float*)d_in[3];
    float* out = (float*)d_out;

    convert_x<<<512, 256>>>(x);                       // 131072 threads
    qmain<<<GRID_N, 256>>>(wpk, wsc, bias, out);      // 112 CTAs, one wave
}